// round 9
// baseline (speedup 1.0000x reference)
#include <cuda_runtime.h>

#define DD    32          // embedding dim D
#define MM    32          // memories per hop
#define LEAKY 0.2f

// scratch: Rh[slot*D + d] for hop>=1 slots; hop-0 logits precomputed
__device__ float g_Rh[131072 * 32];
__device__ float g_logit0[131072];     // logit0[slot] for slot < B*M

__device__ __forceinline__ float warpSum(float v) {
    #pragma unroll
    for (int off = 16; off; off >>= 1) v += __shfl_xor_sync(0xffffffffu, v, off);
    return v;
}
__device__ __forceinline__ float warpMax(float v) {
    #pragma unroll
    for (int off = 16; off; off >>= 1) v = fmaxf(v, __shfl_xor_sync(0xffffffffu, v, off));
    return v;
}

// ---------------------------------------------------------------------------
// MEGA kernel: blockIdx ranges select role.
//   [0, RB)          : r_all gather + fused Rh (warp-per-slot, 8 slots/block)
//                      hop-0 slots additionally fold in item0 -> logit0
//   [RB, RB+HB)      : h_all / t_all gather (float4 granularity)
//   [RB+HB, ...)     : uEmbed + iEmbed contiguous copy (float4)
// ZERO shared memory -> full 228KB L1D carveout -> rel table gets L1 hits.
// Rh mat-vec done entirely in registers via shuffle butterflies.
// ---------------------------------------------------------------------------
__global__ void __launch_bounds__(256) mega_kernel(
        const int*    __restrict__ pos,
        const int*    __restrict__ mh,
        const int*    __restrict__ mr,
        const int*    __restrict__ mt,
        const float4* __restrict__ uE4,
        const float4* __restrict__ iE4,
        const float4* __restrict__ ent4,
        const float4* __restrict__ rel4,
        float4* __restrict__ out_u4,
        float4* __restrict__ out_h4,
        float4* __restrict__ out_t4,
        float4* __restrict__ out_r4,
        int HBM, int RB, int HB, int Ue4, int Ie4, int BM) {
    int blk = blockIdx.x;
    const float* ent = (const float*)ent4;
    const float* iE  = (const float*)iE4;
    const unsigned FULL = 0xffffffffu;

    if (blk < RB) {
        // ---- r_all gather + Rh = R@h, one warp per slot, register-only ----
        int warp = threadIdx.x >> 5, lane = threadIdx.x & 31;
        int slot = blk * 8 + warp;
        if (slot >= HBM) return;

        int r = __ldg(&mr[slot]);
        const float4* src = rel4 + (size_t)r * 256;
        float4* dst = out_r4 + (size_t)slot * 256;

        float4 v[8];
        #pragma unroll
        for (int k = 0; k < 8; k++)       // 8 outstanding loads (L1/L2)
            v[k] = __ldg(&src[k * 32 + lane]);

        int e = __ldg(&mh[slot]);
        float hval = __ldg(&ent[(size_t)e * DD + lane]);

        // h4 = h[4c..4c+3], c = lane&7  (v[k] covers R[4k+(lane>>3)][4c..4c+3])
        int c4 = (lane & 7) * 4;
        float hx = __shfl_sync(FULL, hval, c4 + 0);
        float hy = __shfl_sync(FULL, hval, c4 + 1);
        float hz = __shfl_sync(FULL, hval, c4 + 2);
        float hw = __shfl_sync(FULL, hval, c4 + 3);

        float p[8];
        #pragma unroll
        for (int k = 0; k < 8; k++) {
            __stcs(&dst[k * 32 + lane], v[k]);   // streaming write-out
            p[k] = v[k].x * hx + v[k].y * hy + v[k].z * hz + v[k].w * hw;
        }
        // reduce partials within each 8-lane group
        #pragma unroll
        for (int k = 0; k < 8; k++) {
            p[k] += __shfl_xor_sync(FULL, p[k], 1);
            p[k] += __shfl_xor_sync(FULL, p[k], 2);
            p[k] += __shfl_xor_sync(FULL, p[k], 4);
        }
        // permutation: lane d wants row d, held in p[d>>2] on lanes 8(d&3)+..
        int myk = lane & 7;
        float temp = p[0];
        #pragma unroll
        for (int k = 1; k < 8; k++) if (myk == k) temp = p[k];
        float acc = __shfl_sync(FULL, temp, ((lane & 3) << 3) + (lane >> 2));

        if (slot < BM) {
            // hop 0: fold in item0 = iE[pos[b]] -> scalar logit, skip g_Rh
            int b = slot / MM;
            int p0 = __ldg(&pos[b]);
            float it0 = __ldg(&iE[(size_t)p0 * DD + lane]);   // L1-hot row
            float lg = warpSum(acc * it0);
            if (lane == 0) g_logit0[slot] = lg;
        } else {
            g_Rh[(size_t)slot * DD + lane] = acc;
        }
    } else if (blk < RB + HB) {
        // ---- h_all / t_all gather ----
        int tid = (blk - RB) * 256 + threadIdx.x;
        int N = HBM * 8;                  // 8 float4 per 32-float row
        if (tid < N) {
            int slot = tid >> 3, j = tid & 7;
            int e = __ldg(&mh[slot]);
            __stcs(&out_h4[slot * 8 + j], __ldg(&ent4[(size_t)e * 8 + j]));
        } else if (tid < 2 * N) {
            int t2 = tid - N;
            int slot = t2 >> 3, j = t2 & 7;
            int e = __ldg(&mt[slot]);
            float4 v = __ldg(&ent4[(size_t)e * 8 + j]);
            v.x = v.x > 0.f ? v.x : LEAKY * v.x;
            v.y = v.y > 0.f ? v.y : LEAKY * v.y;
            v.z = v.z > 0.f ? v.z : LEAKY * v.z;
            v.w = v.w > 0.f ? v.w : LEAKY * v.w;
            out_t4[slot * 8 + j] = v;     // re-read by ripple: keep cacheable
        }
    } else {
        // ---- uEmbed + iEmbed copy (contiguous dst, never re-read) ----
        int j = (blk - RB - HB) * 256 + threadIdx.x;
        if (j < Ue4)
            __stcs(&out_u4[j], __ldg(&uE4[j]));
        else if (j < Ue4 + Ie4)
            __stcs(&out_u4[j], __ldg(&iE4[j - Ue4]));
    }
}

// ---------------------------------------------------------------------------
// Hop loop: one warp per batch row b, 8 warps/block. Hop 0 logits were
// precomputed by mega (one coalesced 128B line). Hop>=1 stages Rh in smem.
// Last-wins scatter resolved by inline duplicate scan over pos (L1-hot).
// ---------------------------------------------------------------------------
__global__ void __launch_bounds__(256) ripple_kernel(
        const int*   __restrict__ pos,
        const float* __restrict__ iE,
        const float* __restrict__ t_all,
        const float* __restrict__ W,
        float* __restrict__ out_i,
        int B, int nhop) {
    __shared__ float sW[DD * DD];
    __shared__ float sRh[8][DD * DD];   // 32KB: per-warp Rh tile (hop>=1)
    __shared__ float sIt[8][DD];
    for (int i = threadIdx.x; i < DD * DD; i += blockDim.x) sW[i] = W[i];
    __syncthreads();
    int warp = threadIdx.x >> 5, lane = threadIdx.x & 31;
    int b = blockIdx.x * 8 + warp;
    if (b >= B) return;
    int p = pos[b];

    // last-wins: if any later batch element maps to the same item, we lose.
    bool dup = false;
    for (int j = b + 1 + lane; j < B; j += 32) dup |= (pos[j] == p);
    if (__any_sync(0xffffffffu, dup)) return;

    float item = iE[(size_t)p * DD + lane];
    float* myRh = sRh[warp];
    float* myIt = sIt[warp];

    for (int hop = 0; hop < nhop; hop++) {
        float logit;
        if (hop == 0) {
            // precomputed by mega: lane m reads logit0 of memory slot m
            logit = __ldg(&g_logit0[(size_t)b * MM + lane]);
        } else {
            const float4* Rh4 =
                (const float4*)(g_Rh + (size_t)(hop * B + b) * MM * DD);
            #pragma unroll
            for (int j = 0; j < 8; j++)
                ((float4*)myRh)[j * 32 + lane] = __ldg(&Rh4[j * 32 + lane]);
            myIt[lane] = item;
            __syncwarp();
            // logit[m] on lane m: independent FMAs, conflict-free rotation
            logit = 0.f;
            #pragma unroll
            for (int i = 0; i < DD; i++) {
                int ee = (i + lane) & (DD - 1);
                logit = fmaf(myRh[lane * DD + ee], myIt[ee], logit);
            }
        }
        // softmax across lanes
        float mx = warpMax(logit);
        float ex = expf(logit - mx);
        float prob = ex / warpSum(ex);
        // o[d] = sum_m prob[m] * t[m][d]  (coalesced L2-hot loads)
        const float* tb = t_all + (size_t)(hop * B + b) * MM * DD;
        float o = 0.f;
        #pragma unroll
        for (int m = 0; m < MM; m++) {
            float pm = __shfl_sync(0xffffffffu, prob, m);
            o = fmaf(pm, __ldg(&tb[m * DD + lane]), o);
        }
        // item = (item + o) @ W.T via smem broadcast
        __syncwarp();
        myIt[lane] = item + o;
        __syncwarp();
        float ni = 0.f;
        #pragma unroll
        for (int e = 0; e < DD; e++) {
            int ee = (e + lane) & (DD - 1);
            ni = fmaf(myIt[ee], sW[lane * DD + ee], ni);
        }
        item = ni;
        __syncwarp();
    }
    out_i[(size_t)p * DD + lane] = item;
}

// ---------------------------------------------------------------------------
extern "C" void kernel_launch(void* const* d_in, const int* in_sizes, int n_in,
                              void* d_out, int out_size) {
    const int*   pos = (const int*)d_in[0];
    const int*   mh  = (const int*)d_in[1];
    const int*   mr  = (const int*)d_in[2];
    const int*   mt  = (const int*)d_in[3];
    const float* uE  = (const float*)d_in[4];
    const float* iE  = (const float*)d_in[5];
    const float* ent = (const float*)d_in[6];
    const float* rel = (const float*)d_in[7];
    const float* W   = (const float*)d_in[8];
    float* out = (float*)d_out;

    const int B    = in_sizes[0];             // 2048
    const int HBM  = in_sizes[1];             // H*B*M = 131072
    const int nhop = HBM / (B * MM);          // 2
    const int BM   = B * MM;                  // 65536
    const size_t Ue = (size_t)in_sizes[4];    // USER*D floats
    const size_t Ie = (size_t)in_sizes[5];    // ITEM*D floats

    float* out_u = out;
    float* out_i = out_u + Ue;
    float* out_h = out_i + Ie;
    float* out_t = out_h + (size_t)HBM * DD;
    float* out_r = out_t + (size_t)HBM * DD;

    const int RB  = (HBM + 7) / 8;                      // 16384 r-blocks
    const int HB  = (2 * HBM * 8 + 255) / 256;          // 8192 ht-blocks
    const int Ue4 = (int)(Ue / 4), Ie4 = (int)(Ie / 4);
    const int CB  = (Ue4 + Ie4 + 255) / 256;            // 6250 copy-blocks

    mega_kernel<<<RB + HB + CB, 256>>>(
        pos, mh, mr, mt,
        (const float4*)uE, (const float4*)iE,
        (const float4*)ent, (const float4*)rel,
        (float4*)out_u, (float4*)out_h, (float4*)out_t, (float4*)out_r,
        HBM, RB, HB, Ue4, Ie4, BM);

    ripple_kernel<<<(B + 7) / 8, 256>>>(pos, iE, out_t, W, out_i, B, nhop);
}